// round 5
// baseline (speedup 1.0000x reference)
#include <cuda_runtime.h>
#include <cstdint>

#define N_TOKENS   262144
#define N_EXPERTS  256
#define TOP_K      8

#define LOGITS_ELEMS   ((size_t)N_TOKENS * N_EXPERTS)   // 67108864
#define TOPK_ELEMS     ((size_t)N_TOKENS * TOP_K)       // 2097152

#define BLOCKS   1024
#define THREADS  256

// float -> order-preserving uint key (works for all finite floats)
__device__ __forceinline__ unsigned f2key(float f) {
    unsigned u = __float_as_uint(f);
    return u ^ (0x80000000u | (unsigned)((int)u >> 31));
}
__device__ __forceinline__ float key2f(unsigned k) {
    unsigned u = (k & 0x80000000u) ? (k ^ 0x80000000u) : ~k;
    return __uint_as_float(u);
}

__global__ void zero_hist_kernel(float* __restrict__ hist_out) {
    hist_out[threadIdx.x] = 0.0f;
}

__global__ void __launch_bounds__(THREADS, 8)
moe_router_kernel(const float* __restrict__ logits, float* __restrict__ out) {
    __shared__ int s_hist[N_EXPERTS];

    const int tid  = threadIdx.x;
    const int lane = tid & 31;
    const int warp_global = ((blockIdx.x * THREADS) + tid) >> 5;
    const int n_warps     = (BLOCKS * THREADS) >> 5;  // 8192

    s_hist[tid] = 0;
    __syncthreads();

    float* __restrict__ outLogits = out;
    float* __restrict__ outW = out + LOGITS_ELEMS;
    float* __restrict__ outI = outW + TOPK_ELEMS;

    for (int tok = warp_global; tok < N_TOKENS; tok += n_warps) {
        const float4* row = (const float4*)(logits + (size_t)tok * N_EXPERTS);
        // Lane L owns the CONTIGUOUS index block [8L, 8L+8) so that
        // (lane asc, slot asc) == global index asc — matches lax.top_k
        // tie-breaking (stable: lowest index first on equal values).
        float4 a = row[2 * lane];
        float4 b = row[2 * lane + 1];

        // pass-through copy of logits (reuse the loaded data)
        float4* orow = (float4*)(outLogits + (size_t)tok * N_EXPERTS);
        orow[2 * lane]     = a;
        orow[2 * lane + 1] = b;

        unsigned k[8];
        k[0] = f2key(a.x); k[1] = f2key(a.y); k[2] = f2key(a.z); k[3] = f2key(a.w);
        k[4] = f2key(b.x); k[5] = f2key(b.y); k[6] = f2key(b.z); k[7] = f2key(b.w);

        // ascending scan with strict '>' keeps the LOWEST slot (= lowest index) on ties
        unsigned lmax = 0; int lslot = 0;
        #pragma unroll
        for (int j = 0; j < 8; j++) { if (k[j] > lmax) { lmax = k[j]; lslot = j; } }

        float vmax   = 0.0f;   // round-0 (largest) value, broadcast to all lanes
        float myval  = 0.0f;   // lane r (r<8) keeps round-r selected value
        int   myidx  = 0;

        #pragma unroll
        for (int r = 0; r < TOP_K; r++) {
            unsigned g = __reduce_max_sync(0xffffffffu, lmax);
            unsigned bal = __ballot_sync(0xffffffffu, lmax == g);
            int win = __ffs(bal) - 1;               // lowest lane = lowest index block
            int wslot = __shfl_sync(0xffffffffu, lslot, win);
            int idx = win * 8 + wslot;              // contiguous mapping
            float val = key2f(g);
            if (r == 0) vmax = val;
            if (lane == r) { myval = val; myidx = idx; }
            if (lane == win) {
                k[lslot] = 0u;
                lmax = 0; lslot = 0;
                #pragma unroll
                for (int j = 0; j < 8; j++) { if (k[j] > lmax) { lmax = k[j]; lslot = j; } }
            }
        }

        // softmax over the 8 selected logits (== renormalized top-k softmax:
        // the full 256-wide denominator cancels under renormalization)
        float e = __expf(myval - vmax);
        float s = e;
        s += __shfl_xor_sync(0xffffffffu, s, 1);
        s += __shfl_xor_sync(0xffffffffu, s, 2);
        s += __shfl_xor_sync(0xffffffffu, s, 4);

        if (lane < TOP_K) {
            outW[(size_t)tok * TOP_K + lane] = e / s;
            outI[(size_t)tok * TOP_K + lane] = (float)myidx;
            atomicAdd(&s_hist[myidx], 1);
        }
    }

    __syncthreads();
    float* __restrict__ outH = out + LOGITS_ELEMS + 2 * TOPK_ELEMS;
    int c = s_hist[tid];
    if (c > 0) atomicAdd(&outH[tid], (float)c);
}

extern "C" void kernel_launch(void* const* d_in, const int* in_sizes, int n_in,
                              void* d_out, int out_size) {
    const float* logits = (const float*)d_in[0];
    float* out = (float*)d_out;

    float* hist_region = out + LOGITS_ELEMS + 2 * TOPK_ELEMS;
    zero_hist_kernel<<<1, N_EXPERTS>>>(hist_region);
    moe_router_kernel<<<BLOCKS, THREADS>>>(logits, out);
}

// round 6
// speedup vs baseline: 1.5945x; 1.5945x over previous
#include <cuda_runtime.h>
#include <cstdint>

#define N_TOKENS   262144
#define N_EXPERTS  256
#define TOP_K      8

#define LOGITS_ELEMS   ((size_t)N_TOKENS * N_EXPERTS)   // 67108864
#define TOPK_ELEMS     ((size_t)N_TOKENS * TOP_K)       // 2097152

#define BLOCKS   888           // 148 SMs * 6 blocks -> single clean wave
#define THREADS  256
#define WARPS_PER_BLOCK (THREADS / 32)
#define MAX_SURV 16

// float -> order-preserving uint key (finite floats)
__device__ __forceinline__ unsigned f2key(float f) {
    unsigned u = __float_as_uint(f);
    return u ^ (0x80000000u | (unsigned)((int)u >> 31));
}
__device__ __forceinline__ float key2f(unsigned k) {
    unsigned u = (k & 0x80000000u) ? (k ^ 0x80000000u) : ~k;
    return __uint_as_float(u);
}

__global__ void zero_hist_kernel(float* __restrict__ hist_out) {
    hist_out[threadIdx.x] = 0.0f;
}

__global__ void __launch_bounds__(THREADS, 6)
moe_router_kernel(const float* __restrict__ logits, float* __restrict__ out) {
    __shared__ int   s_hist[N_EXPERTS];
    __shared__ uint2 s_surv[WARPS_PER_BLOCK][MAX_SURV];

    const int tid  = threadIdx.x;
    const int lane = tid & 31;
    const int wip  = tid >> 5;
    const int warp_global = blockIdx.x * WARPS_PER_BLOCK + wip;
    const int n_warps     = BLOCKS * WARPS_PER_BLOCK;

    s_hist[tid] = 0;
    __syncthreads();

    float* __restrict__ outW = out + LOGITS_ELEMS;
    float* __restrict__ outI = outW + TOPK_ELEMS;
    uint2* buf = s_surv[wip];

    for (int tok = warp_global; tok < N_TOKENS; tok += n_warps) {
        const float4* row = (const float4*)(logits + (size_t)tok * N_EXPERTS);
        // Lane L owns contiguous indices [8L, 8L+8): (lane asc, slot asc) == index asc
        float4 a = row[2 * lane];
        float4 b = row[2 * lane + 1];

        float4* orow = (float4*)(out + (size_t)tok * N_EXPERTS);
        orow[2 * lane]     = a;   // pass-through logits copy (reuse loaded data)
        orow[2 * lane + 1] = b;

        float f0=a.x, f1=a.y, f2=a.z, f3=a.w, f4=b.x, f5=b.y, f6=b.z, f7=b.w;

        // per-lane max (7 FMNMX)
        float m = fmaxf(fmaxf(fmaxf(f0,f1), fmaxf(f2,f3)),
                        fmaxf(fmaxf(f4,f5), fmaxf(f6,f7)));

        // T0 = ~8th-largest of the 32 lane maxes (lower bound of global 8th).
        // Duplicate maxes get zeroed together -> T0 only shrinks (still a valid bound).
        unsigned u = f2key(m);
        unsigned g0 = 0, g = 0;
        #pragma unroll
        for (int r = 0; r < TOP_K; r++) {
            g = __reduce_max_sync(0xffffffffu, u);
            if (r == 0) g0 = g;          // global max key
            u = (u == g) ? 0u : u;
        }
        float T0f = key2f(g);

        // survivor counts (v >= T0f; float compare == key compare, monotonic)
        bool p0=f0>=T0f, p1=f1>=T0f, p2=f2>=T0f, p3=f3>=T0f;
        bool p4=f4>=T0f, p5=f5>=T0f, p6=f6>=T0f, p7=f7>=T0f;
        int cnt = (int)p0+(int)p1+(int)p2+(int)p3+(int)p4+(int)p5+(int)p6+(int)p7;

        // inclusive prefix scan over lanes (index order)
        int pfx = cnt;
        #pragma unroll
        for (int d = 1; d < 32; d <<= 1) {
            int t = __shfl_up_sync(0xffffffffu, pfx, d);
            if (lane >= d) pfx += t;
        }
        int total = __shfl_sync(0xffffffffu, pfx, 31);
        int base  = pfx - cnt;

        if (total <= MAX_SURV && total >= TOP_K) {
            // ---- fast path: compact survivors to smem in index order ----
            int c = base;
            if (p0) buf[c++] = make_uint2(__float_as_uint(f0), (unsigned)(lane*8+0));
            if (p1) buf[c++] = make_uint2(__float_as_uint(f1), (unsigned)(lane*8+1));
            if (p2) buf[c++] = make_uint2(__float_as_uint(f2), (unsigned)(lane*8+2));
            if (p3) buf[c++] = make_uint2(__float_as_uint(f3), (unsigned)(lane*8+3));
            if (p4) buf[c++] = make_uint2(__float_as_uint(f4), (unsigned)(lane*8+4));
            if (p5) buf[c++] = make_uint2(__float_as_uint(f5), (unsigned)(lane*8+5));
            if (p6) buf[c++] = make_uint2(__float_as_uint(f6), (unsigned)(lane*8+6));
            if (p7) buf[c++] = make_uint2(__float_as_uint(f7), (unsigned)(lane*8+7));
            __syncwarp();

            // lanes 0..total-1 each own one survivor; rank by (value desc, idx asc)
            uint2 sv2  = buf[lane & (MAX_SURV - 1)];
            bool valid = lane < total;
            float sval = __uint_as_float(sv2.x);
            unsigned sidx = sv2.y;
            // packed 64-bit sort key; invalid lanes -> 0 (never ranks above a survivor)
            unsigned long long kk =
                valid ? ((((unsigned long long)f2key(sval)) << 8)
                         | (unsigned long long)(255u - sidx))
                      : 0ull;
            int rank = 0;
            #pragma unroll
            for (int d = 1; d < MAX_SURV; d++) {
                unsigned long long ok = __shfl_xor_sync(0xffffffffu, kk, d, MAX_SURV);
                rank += (ok > kk);
            }

            bool win8 = valid && (rank < TOP_K);
            float vmax = key2f(g0);
            float ex = win8 ? __expf(sval - vmax) : 0.0f;
            float s = ex;
            #pragma unroll
            for (int d = 1; d < MAX_SURV; d <<= 1)
                s += __shfl_xor_sync(0xffffffffu, s, d, MAX_SURV);

            if (win8) {
                outW[(size_t)tok * TOP_K + rank] = __fdividef(ex, s);
                outI[(size_t)tok * TOP_K + rank] = (float)sidx;
                atomicAdd(&s_hist[sidx], 1);
            }
            __syncwarp();   // protect buf across loop iterations
        } else {
            // ---- fallback: exact 8-round selection (proven R5 path) ----
            unsigned k[8];
            k[0]=f2key(f0); k[1]=f2key(f1); k[2]=f2key(f2); k[3]=f2key(f3);
            k[4]=f2key(f4); k[5]=f2key(f5); k[6]=f2key(f6); k[7]=f2key(f7);

            unsigned lmax = 0; int lslot = 0;
            #pragma unroll
            for (int j = 0; j < 8; j++) { if (k[j] > lmax) { lmax = k[j]; lslot = j; } }

            unsigned mykey = 0; int myidx = 0;
            #pragma unroll
            for (int r = 0; r < TOP_K; r++) {
                unsigned gg  = __reduce_max_sync(0xffffffffu, lmax);
                unsigned bal = __ballot_sync(0xffffffffu, lmax == gg);
                int win   = __ffs(bal) - 1;                    // lowest lane = lowest idx
                int wslot = __shfl_sync(0xffffffffu, lslot, win);
                if (lane == r) { mykey = gg; myidx = win * 8 + wslot; }
                if (lane == win) {
                    k[lslot] = 0u;
                    lmax = 0; lslot = 0;
                    #pragma unroll
                    for (int j = 0; j < 8; j++) { if (k[j] > lmax) { lmax = k[j]; lslot = j; } }
                }
            }

            float vmax = key2f(__shfl_sync(0xffffffffu, mykey, 0));
            float myval = (lane < TOP_K) ? key2f(mykey) : vmax;  // lanes>=8: e=1, unused
            float e = __expf(myval - vmax);
            float s = e;
            s += __shfl_xor_sync(0xffffffffu, s, 1);
            s += __shfl_xor_sync(0xffffffffu, s, 2);
            s += __shfl_xor_sync(0xffffffffu, s, 4);   // sums stay within 8-lane groups

            if (lane < TOP_K) {
                outW[(size_t)tok * TOP_K + lane] = __fdividef(e, s);
                outI[(size_t)tok * TOP_K + lane] = (float)myidx;
                atomicAdd(&s_hist[myidx], 1);
            }
        }
    }

    __syncthreads();
    float* __restrict__ outH = out + LOGITS_ELEMS + 2 * TOPK_ELEMS;
    int c = s_hist[tid];
    if (c > 0) atomicAdd(&outH[tid], (float)c);
}

extern "C" void kernel_launch(void* const* d_in, const int* in_sizes, int n_in,
                              void* d_out, int out_size) {
    const float* logits = (const float*)d_in[0];
    float* out = (float*)d_out;

    float* hist_region = out + LOGITS_ELEMS + 2 * TOPK_ELEMS;
    zero_hist_kernel<<<1, N_EXPERTS>>>(hist_region);
    moe_router_kernel<<<BLOCKS, THREADS>>>(logits, out);
}